// round 16
// baseline (speedup 1.0000x reference)
#include <cuda_runtime.h>
#include <cuda_bf16.h>

// GaussianBlur: separable depthwise Gaussian (sigma=2), reflect_101,
// 32x3x512x512 fp32.  out = blur(x) + 254/255  (affine folded through blur).
//
// R14 (pipelining) was neutral -> horizontal LDS latency is not the stall;
// overhead slots are. R15 = R12 base + HT=8 horizontal:
//   - 5 LDS.128 per 8 outputs (1.25 smem floats/output, was 4) -> -37.5%
//     crossbar wavefronts in the L1-heaviest pass
//   - one task-decode + loop iteration per 8 outputs (3.2 iters, was 6.4)
//   - 2 contiguous STG.128 per task, still fully coalesced per warp
// R6's HT=8 failure was the old 48-float vertical window (regs 82); with the
// 19-reg rolling window the horizontal transients (20+8 regs) fit the
// 51-reg / 4 CTA budget.

#define RAD   6
#define KS    13
#define IMGN  512
#define TW    128
#define TH    64
#define SW    (TW + 2 * RAD)        // 140
#define SWP   144                   // padded row stride (floats), %4==0
#define NTHR  320
#define VT    32                    // vertical outputs per task
#define VROWS (VT + 2 * RAD)        // 44 rows per strip
#define W     19                    // rolling window slots (13 taps + D=6)
#define PRE   18                    // prologue loads (W-1)
#define VTASKS (SW * (TH / VT))     // 280
#define HT    8                     // x outputs per horizontal task
#define HSEG  (TW / HT)             // 16
#define HTASKS (HSEG * TH)          // 1024

// 13-tap renormalized Gaussian (sigma=2): exp(-t^2/8)/S, t=-6..6,
// S = 5.00812248. Compile-time -> FFMA-imm under full unroll.
__device__ __forceinline__ constexpr float kg(int j) {
    constexpr float K[KS] = {
        2.2181965e-03f, 8.7731373e-03f, 2.7023174e-02f, 6.4825160e-02f,
        1.2110944e-01f, 1.7621313e-01f,
        1.9967563e-01f,
        1.7621313e-01f, 1.2110944e-01f, 6.4825160e-02f, 2.7023174e-02f,
        8.7731373e-03f, 2.2181965e-03f
    };
    return K[j];
}

__device__ __forceinline__ int mirror(int v) {
    // reflect_101, valid for |overhang| <= RAD
    const int a = ::abs(v);
    return ::min(a, 2 * (IMGN - 1) - a);
}

__global__ __launch_bounds__(NTHR, 4)
void gaussian_blur_fused(const float* __restrict__ in, float* __restrict__ out) {
    __shared__ __align__(16) float s_mid[TH * SWP];   // 64*144*4 = 36864 B

    const int x0 = blockIdx.x * TW;
    const int y0 = blockIdx.y * TH;
    const float* __restrict__ img  = in  + (size_t)blockIdx.z * (IMGN * IMGN);
    float*       __restrict__ oimg = out + (size_t)blockIdx.z * (IMGN * IMGN);
    const int tid = threadIdx.x;

    // ---- vertical pass (R12 verbatim): rolling W-reg window, D=6 lookahead ----
    if (tid < VTASKS) {
        int x = tid, strip = 0;
        if (x >= SW) { x -= SW; strip = 1; }
        const int yy = y0 + strip * VT - RAD;

        const int  gx   = mirror(x0 + x - RAD);     // task-constant
        const bool y_ok = (yy >= 0) && (yy + VROWS <= IMGN);

        float w[W];
        if (y_ok) {
            const float* __restrict__ p = img + (size_t)yy * IMGN + gx;
            #pragma unroll
            for (int r = 0; r < PRE; ++r)
                w[r] = p[r * IMGN];                  // batched prologue, MLP=18
            #pragma unroll
            for (int i = 0; i < VT; ++i) {
                if (i + PRE < VROWS)                 // compile-time per iter
                    w[(i + PRE) % W] = p[(i + PRE) * IMGN];
                float acc = 0.0f;
                #pragma unroll
                for (int j = 0; j < KS; ++j)
                    acc = fmaf(w[(i + j) % W], kg(j), acc);
                s_mid[(strip * VT + i) * SWP + x] = acc;
            }
        } else {
            #pragma unroll
            for (int r = 0; r < PRE; ++r)
                w[r] = img[(size_t)mirror(yy + r) * IMGN + gx];
            #pragma unroll
            for (int i = 0; i < VT; ++i) {
                if (i + PRE < VROWS)
                    w[(i + PRE) % W] =
                        img[(size_t)mirror(yy + i + PRE) * IMGN + gx];
                float acc = 0.0f;
                #pragma unroll
                for (int j = 0; j < KS; ++j)
                    acc = fmaf(w[(i + j) % W], kg(j), acc);
                s_mid[(strip * VT + i) * SWP + x] = acc;
            }
        }
    }
    __syncthreads();

    // ---- horizontal pass: 8-output tasks ----
    // 20-float window = exactly 5 aligned LDS.128; 2 coalesced STG.128.
    const float OFS = 254.0f / 255.0f;
    #pragma unroll
    for (int t = tid; t < HTASKS; t += NTHR) {
        const int row = t >> 4;              // HSEG == 16
        const int seg = t & 15;

        const float4* __restrict__ src =
            (const float4*)(s_mid + row * SWP) + seg * 2;
        const float4 q0 = src[0], q1 = src[1], q2 = src[2],
                     q3 = src[3], q4 = src[4];
        const float m[HT + KS - 1] = {
            q0.x, q0.y, q0.z, q0.w,  q1.x, q1.y, q1.z, q1.w,
            q2.x, q2.y, q2.z, q2.w,  q3.x, q3.y, q3.z, q3.w,
            q4.x, q4.y, q4.z, q4.w
        };

        float o[HT];
        #pragma unroll
        for (int i = 0; i < HT; ++i) {
            float acc = OFS;                 // fold affine offset
            #pragma unroll
            for (int j = 0; j < KS; ++j)
                acc = fmaf(m[i + j], kg(j), acc);
            o[i] = acc;
        }

        float4* dst = (float4*)(oimg + (size_t)(y0 + row) * IMGN + x0 + seg * HT);
        dst[0] = make_float4(o[0], o[1], o[2], o[3]);
        dst[1] = make_float4(o[4], o[5], o[6], o[7]);
    }
}

extern "C" void kernel_launch(void* const* d_in, const int* in_sizes, int n_in,
                              void* d_out, int out_size) {
    const float* in = (const float*)d_in[0];
    float* out = (float*)d_out;
    const int n_imgs = in_sizes[0] / (IMGN * IMGN);   // 96
    dim3 grid(IMGN / TW, IMGN / TH, n_imgs);          // (4, 8, 96)
    gaussian_blur_fused<<<grid, NTHR>>>(in, out);
}

// round 17
// speedup vs baseline: 1.1420x; 1.1420x over previous
#include <cuda_runtime.h>
#include <cuda_bf16.h>

// GaussianBlur: separable depthwise Gaussian (sigma=2), reflect_101,
// 32x3x512x512 fp32.  out = blur(x) + 254/255  (affine folded through blur).
//
// R15 -> R16: HT=8 falsified twice (issue starves); R12 structure kept
// verbatim, but CTA granularity halved: TH=32, NTHR=160, 8 CTAs/SM.
//  - barrier stalls decorrelate: 8 independent CTAs per SM (was 4), so a
//    CTA parked at __syncthreads or in its DRAM prologue is covered by 7
//    others instead of 3.
//  - grid tail (5.19 waves) waste halves with half-size CTAs.
//  - same read-amp (VT=32 strips already re-read the 12-row halo), same
//    regs (48), same 40-warp/SM pool.

#define RAD   6
#define KS    13
#define IMGN  512
#define TW    128
#define TH    32
#define SW    (TW + 2 * RAD)        // 140
#define SWP   144                   // padded row stride (floats), %4==0
#define NTHR  160
#define VT    32                    // vertical outputs per task (one strip)
#define VROWS (VT + 2 * RAD)        // 44 rows
#define W     19                    // rolling window slots (13 taps + D=6)
#define PRE   18                    // prologue loads (W-1)
#define VTASKS SW                   // 140 (single strip)
#define HT    4                     // horizontal outputs per task (one float4)
#define HTASKS ((TW / HT) * TH)     // 1024

// 13-tap renormalized Gaussian (sigma=2): exp(-t^2/8)/S, t=-6..6,
// S = 5.00812248. Compile-time -> FFMA-imm under full unroll.
__device__ __forceinline__ constexpr float kg(int j) {
    constexpr float K[KS] = {
        2.2181965e-03f, 8.7731373e-03f, 2.7023174e-02f, 6.4825160e-02f,
        1.2110944e-01f, 1.7621313e-01f,
        1.9967563e-01f,
        1.7621313e-01f, 1.2110944e-01f, 6.4825160e-02f, 2.7023174e-02f,
        8.7731373e-03f, 2.2181965e-03f
    };
    return K[j];
}

__device__ __forceinline__ int mirror(int v) {
    // reflect_101, valid for |overhang| <= RAD
    const int a = ::abs(v);
    return ::min(a, 2 * (IMGN - 1) - a);
}

__global__ __launch_bounds__(NTHR, 8)
void gaussian_blur_fused(const float* __restrict__ in, float* __restrict__ out) {
    __shared__ __align__(16) float s_mid[TH * SWP];   // 32*144*4 = 18432 B

    const int x0 = blockIdx.x * TW;
    const int y0 = blockIdx.y * TH;
    const float* __restrict__ img  = in  + (size_t)blockIdx.z * (IMGN * IMGN);
    float*       __restrict__ oimg = out + (size_t)blockIdx.z * (IMGN * IMGN);
    const int tid = threadIdx.x;

    // ---- vertical pass: 140 tasks; rolling W-reg window, D=6 lookahead ----
    if (tid < VTASKS) {
        const int x  = tid;
        const int yy = y0 - RAD;

        const int  gx   = mirror(x0 + x - RAD);     // task-constant
        const bool y_ok = (yy >= 0) && (yy + VROWS <= IMGN);

        float w[W];
        if (y_ok) {
            const float* __restrict__ p = img + (size_t)yy * IMGN + gx;
            #pragma unroll
            for (int r = 0; r < PRE; ++r)
                w[r] = p[r * IMGN];                  // batched prologue, MLP=18
            #pragma unroll
            for (int i = 0; i < VT; ++i) {
                if (i + PRE < VROWS)                 // compile-time per iter
                    w[(i + PRE) % W] = p[(i + PRE) * IMGN];
                float acc = 0.0f;
                #pragma unroll
                for (int j = 0; j < KS; ++j)
                    acc = fmaf(w[(i + j) % W], kg(j), acc);
                s_mid[i * SWP + x] = acc;
            }
        } else {
            #pragma unroll
            for (int r = 0; r < PRE; ++r)
                w[r] = img[(size_t)mirror(yy + r) * IMGN + gx];
            #pragma unroll
            for (int i = 0; i < VT; ++i) {
                if (i + PRE < VROWS)
                    w[(i + PRE) % W] =
                        img[(size_t)mirror(yy + i + PRE) * IMGN + gx];
                float acc = 0.0f;
                #pragma unroll
                for (int j = 0; j < KS; ++j)
                    acc = fmaf(w[(i + j) % W], kg(j), acc);
                s_mid[i * SWP + x] = acc;
            }
        }
    }
    __syncthreads();

    // ---- horizontal pass: s_mid -> registers -> global (coalesced) ----
    // task: 4 consecutive x outputs of one row; 16-float window = exactly
    // 4 aligned LDS.128. Warp lanes -> consecutive x-segments: coalesced
    // LDS.128 and STG.128.
    const float OFS = 254.0f / 255.0f;
    for (int t = tid; t < HTASKS; t += NTHR) {
        const int row = t >> 5;          // TW/HT == 32
        const int xs  = t & 31;

        const float4* __restrict__ src =
            (const float4*)(s_mid + row * SWP) + xs;
        const float4 v0 = src[0], v1 = src[1], v2 = src[2], v3 = src[3];
        const float m[HT + KS - 1] = {
            v0.x, v0.y, v0.z, v0.w,  v1.x, v1.y, v1.z, v1.w,
            v2.x, v2.y, v2.z, v2.w,  v3.x, v3.y, v3.z, v3.w
        };

        float o[HT];
        #pragma unroll
        for (int i = 0; i < HT; ++i) {
            float acc = OFS;             // fold affine offset
            #pragma unroll
            for (int j = 0; j < KS; ++j)
                acc = fmaf(m[i + j], kg(j), acc);
            o[i] = acc;
        }

        *(float4*)(oimg + (size_t)(y0 + row) * IMGN + x0 + xs * HT) =
            make_float4(o[0], o[1], o[2], o[3]);
    }
}

extern "C" void kernel_launch(void* const* d_in, const int* in_sizes, int n_in,
                              void* d_out, int out_size) {
    const float* in = (const float*)d_in[0];
    float* out = (float*)d_out;
    const int n_imgs = in_sizes[0] / (IMGN * IMGN);   // 96
    dim3 grid(IMGN / TW, IMGN / TH, n_imgs);          // (4, 16, 96)
    gaussian_blur_fused<<<grid, NTHR>>>(in, out);
}